// round 17
// baseline (speedup 1.0000x reference)
#include <cuda_runtime.h>
#include <cuda_fp16.h>
#include <mma.h>
#include <stdint.h>
#include <stddef.h>
using namespace nvcuda;

#define SEQ 512
#define BATCH 256
#define INSZ 256
#define HID 128
#define GATES 512
#define OUTSZ 1000
#define M_TOT (SEQ*BATCH)
#define NTILES 1024
#define LDA 264
#define LDC 68
#define HSTR 136

__device__ __half g_wih[GATES*INSZ];
__device__ __half g_whh16[GATES*HID];
__device__ float  g_bias[GATES];
__device__ float  g_xproj[(size_t)M_TOT*GATES];
__device__ float  g_hlast[BATCH*HID];
__device__ int    g_flags[NTILES];
__device__ int    g_tilectr;

extern __shared__ char dynsm[];

__device__ __forceinline__ uint32_t s2u(const void* p){
    uint32_t a; asm("{ .reg .u64 t; cvta.to.shared.u64 t, %1; cvt.u32.u64 %0, t; }":"=r"(a):"l"(p)); return a;
}
__device__ __forceinline__ void ldsm4(uint32_t* r, uint32_t a){
    asm volatile("ldmatrix.sync.aligned.m8n8.x4.shared.b16 {%0,%1,%2,%3},[%4];"
        :"=r"(r[0]),"=r"(r[1]),"=r"(r[2]),"=r"(r[3]):"r"(a));
}
__device__ __forceinline__ void mma16816h(uint32_t* d, const uint32_t* A, const uint32_t* B){
    asm volatile("mma.sync.aligned.m16n8k16.row.col.f16.f16.f16.f16 "
        "{%0,%1},{%2,%3,%4,%5},{%6,%7},{%0,%1};"
        :"+r"(d[0]),"+r"(d[1])
        :"r"(A[0]),"r"(A[1]),"r"(A[2]),"r"(A[3]),"r"(B[0]),"r"(B[1]));
}
__device__ __forceinline__ float tanha(float x){ float r; asm("tanh.approx.f32 %0,%1;":"=f"(r):"f"(x)); return r; }
__device__ __forceinline__ float sigf(float x){ return fmaf(0.5f, tanha(0.5f*x), 0.5f); }
#define CPA16(d,s) asm volatile("cp.async.cg.shared.global [%0],[%1],16;"::"r"(s2u(d)),"l"(s))
#define CPA4(d,s)  asm volatile("cp.async.ca.shared.global [%0],[%1],4;"::"r"(s2u(d)),"l"(s))

__device__ __forceinline__ void waitflag(const int* p){
    while (*(volatile const int*)p == 0) __nanosleep(128);
    __threadfence();
}

// ---------------- prep ----------------
__global__ void k_prep(const float* __restrict__ w_ih, const float* __restrict__ w_hh,
                       const float* __restrict__ b_ih, const float* __restrict__ b_hh){
    int i = blockIdx.x*blockDim.x + threadIdx.x;
    if (i < GATES*INSZ) g_wih[i] = __float2half_rn(w_ih[i]);
    if (i < GATES*HID)  g_whh16[i] = __float2half_rn(w_hh[i]);
    if (i < GATES)      g_bias[i] = b_ih[i] + b_hh[i];
    if (i < NTILES)     g_flags[i] = 0;
    if (i == 0)         g_tilectr = 0;
}
__global__ void k_dummy(){}

// ---------------- fused producer(gemm) / consumer(recurrence) ----------------
__device__ __forceinline__ void stageB(__half* Bs, int n0, int tid){
    for (int idx=tid; idx<64*32; idx+=512){
        int row=idx>>5, q=idx&31;
        CPA16(Bs + row*LDA + q*8, g_wih + (size_t)(n0+row)*256 + q*8);
    }
}

__global__ void __launch_bounds__(512,1) k_fused(const float* __restrict__ x){
    int bid = blockIdx.x, tid = threadIdx.x;

    if (bid >= 32){
        // =============== GEMM producer (unchanged) ===============
        __half* As  = (__half*)dynsm;
        __half* Bs0 = As + 128*LDA;
        __half* Bs1 = Bs0 + 64*LDA;
        float*  Cs  = (float*)(Bs1 + 64*LDA);
        __half* Bsel[2] = {Bs0, Bs1};
        __shared__ int tile_sm;
        int warp=tid>>5, wm=warp>>2, wn=warp&3;
        for(;;){
            if (tid==0) tile_sm = atomicAdd(&g_tilectr, 1);
            __syncthreads();
            int tile = tile_sm;
            if (tile >= NTILES) return;
            int m0 = tile*128;

            stageB(Bs0, 0, tid);
            asm volatile("cp.async.commit_group;");
            for (int idx=tid; idx<128*64; idx+=512){
                int row=idx>>6, q=idx&63;
                float4 v = ((const float4*)(x+(size_t)(m0+row)*INSZ))[q];
                __half2* dst=(__half2*)(As+row*LDA);
                dst[2*q]=__floats2half2_rn(v.x,v.y); dst[2*q+1]=__floats2half2_rn(v.z,v.w);
            }
            for (int nt=0; nt<8; nt++){
                int n0=nt*64;
                if (nt<7){
                    stageB(Bsel[(nt+1)&1], (nt+1)*64, tid);
                    asm volatile("cp.async.commit_group;");
                    asm volatile("cp.async.wait_group 1;");
                } else {
                    asm volatile("cp.async.wait_group 0;");
                }
                __syncthreads();
                __half* Bs = Bsel[nt&1];

                wmma::fragment<wmma::accumulator,16,16,16,float> c[2];
                for (int i=0;i<2;i++) wmma::fill_fragment(c[i],0.0f);
#pragma unroll
                for (int kt=0;kt<16;kt++){
                    int k=kt*16;
                    wmma::fragment<wmma::matrix_a,16,16,16,__half,wmma::row_major> a[2];
                    wmma::fragment<wmma::matrix_b,16,16,16,__half,wmma::col_major> b;
                    for (int i=0;i<2;i++) wmma::load_matrix_sync(a[i],As+(wm*32+i*16)*LDA+k,LDA);
                    wmma::load_matrix_sync(b,Bs+(wn*16)*LDA+k,LDA);
                    for (int i=0;i<2;i++) wmma::mma_sync(c[i],a[i],b,c[i]);
                }
                for (int i=0;i<2;i++)
                    wmma::store_matrix_sync(&Cs[(wm*32+i*16)*LDC+wn*16],c[i],LDC,wmma::mem_row_major);
                __syncthreads();
                for (int t=tid; t<128*16; t+=512){
                    int r=t>>4, cq=t&15;
                    float4 v=((float4*)Cs)[r*(LDC/4)+cq]; int c0=cq*4;
                    v.x+=g_bias[n0+c0]; v.y+=g_bias[n0+c0+1]; v.z+=g_bias[n0+c0+2]; v.w+=g_bias[n0+c0+3];
                    ((float4*)(g_xproj+(size_t)(m0+r)*GATES+n0))[cq]=v;
                }
                __syncthreads();
            }
            if (tid==0){ __threadfence(); atomicExch(&g_flags[tile], 1); }
        }
    }

    // ====== recurrence: flipped MMA + SYMMETRIC warp split ======
    // 16 warps = 8 cg x 2 kh. Each warp: acts on its own m-half (kh0->d0 cols,
    // kh1->d1 cols), exchanges partner-half partials via redbuf, stages its
    // own x half. Balanced critical paths, same 2 bars/step.
    __half* wsh  = (__half*)dynsm;                     // init only [512][128]
    float*  xsm  = (float*)dynsm;                      // after init: [2][8][32][20f]
    __half* hb   = (__half*)(dynsm+131072);            // [2][8][HSTR]
    char*   redb = dynsm + 131072 + 2*8*HSTR*2;        // [16 warps][32][16B] = 8KB
    int w=tid>>5, lane=tid&31;
    int cg=w>>1, kh=w&1;
    for (int i=tid; i<GATES*HID/8; i+=512) ((uint4*)wsh)[i] = ((const uint4*)g_whh16)[i];
    for (int i=tid; i<2*8*HSTR/2; i+=512) ((__half2*)hb)[i] = __floats2half2_rn(0.f,0.f);
    __syncthreads();

    uint32_t A[4][4][4];
#pragma unroll
    for (int g=0; g<4; g++)
#pragma unroll
        for (int kt=0; kt<4; kt++)
            ldsm4(A[g][kt], s2u(wsh + (size_t)(g*128 + cg*16 + (lane&15))*128
                                    + kh*64 + kt*16 + (lane>>4)*8));
    __syncthreads();                                   // wsh free -> xsm

    int half = (bid>=16) ? 1 : 0;
    // stage own cp-half: 8 cp.async per thread
#define STAGEX(tt) do{ int _t=(tt); if(_t>SEQ-1)_t=SEQ-1;                            \
    const float* _s = g_xproj + ((size_t)_t*BATCH + bid*8)*GATES;                    \
    float* _d = xsm + (_t&1)*5120 + (cg*32+lane)*20;                                 \
    _Pragma("unroll") for (int e=0; e<8; e++){                                       \
        int gg=e>>1, rp=e&1, ix=gg*4 + kh*2 + rp;                                    \
        int row = 2*(lane&3)+rp, cc_ = cg*16 + (lane>>2) + 8*kh;                     \
        CPA4(_d+ix, _s + (size_t)row*GATES + gg*128 + cc_);                          \
    } asm volatile("cp.async.commit_group;"); }while(0)

    if (w==1 && lane<11){ int tf=lane; if(tf>SEQ-1)tf=SEQ-1; waitflag(&g_flags[2*tf+half]); }
    __syncthreads();
    STAGEX(0);
    STAGEX(1);

    float cc0=0.f, cc1=0.f, h0f=0.f, h1f=0.f;
    int mycol = cg*16 + (lane>>2) + 8*kh;              // acted column
    int r0a   = 2*(lane&3);                            // acted row pair

    for (int t=0; t<SEQ; t++){
        if ((t&7)==0 && w==1 && lane<8){               // confirm flags t+3..t+10
            int tf=t+3+lane; if (tf>SEQ-1) tf=SEQ-1;
            waitflag(&g_flags[2*tf+half]);
        }
        __syncthreads();                               // h(t-1) visible + flags

        uint32_t Bf[4][2];
        {
            uint32_t hba = s2u(hb + (t&1)*8*HSTR + (lane&7)*HSTR + kh*64 + (lane>>3)*8);
            uint32_t q[4];
            ldsm4(q, hba);         Bf[0][0]=q[0]; Bf[0][1]=q[1]; Bf[1][0]=q[2]; Bf[1][1]=q[3];
            ldsm4(q, hba + 64);    Bf[2][0]=q[0]; Bf[2][1]=q[1]; Bf[3][0]=q[2]; Bf[3][1]=q[3];
        }
        uint32_t acc[4][2];
#pragma unroll
        for (int g=0; g<4; g++){ acc[g][0]=0u; acc[g][1]=0u; }
#pragma unroll
        for (int kt=0; kt<4; kt++)
#pragma unroll
            for (int g=0; g<4; g++) mma16816h(acc[g], A[g][kt], Bf[kt]);

        // publish partner-half partials (the d-half I do NOT act on)
        int ph = kh^1;
        uint4 P;
        P.x = acc[0][ph]; P.y = acc[1][ph]; P.z = acc[2][ph]; P.w = acc[3][ph];
        *(uint4*)(redb + w*512 + lane*16) = P;
        __syncthreads();                               // partials visible

        // combine: own-half acc + partner's matching partial + x (own half)
        asm volatile("cp.async.wait_group 1;");        // x[t] resident
        uint4 Q = *(uint4*)(redb + (w^1)*512 + lane*16);
        const float* xe = xsm + (t&1)*5120 + (cg*32+lane)*20;
        __half2 pre[4];
        {
            uint32_t qa[4] = {Q.x, Q.y, Q.z, Q.w};
#pragma unroll
            for (int g=0; g<4; g++){
                float2 xv = *(const float2*)(xe + g*4 + kh*2);
                __half2 s = __hadd2(*(const __half2*)&acc[g][kh], *(const __half2*)&qa[g]);
                pre[g] = __hadd2(s, __floats2half2_rn(xv.x, xv.y));
            }
        }
        float2 iv=__half22float2(pre[0]), fv=__half22float2(pre[1]);
        float2 gv=__half22float2(pre[2]), ov=__half22float2(pre[3]);
        cc0 = sigf(fv.x)*cc0 + sigf(iv.x)*tanha(gv.x);
        cc1 = sigf(fv.y)*cc1 + sigf(iv.y)*tanha(gv.y);
        h0f = sigf(ov.x)*tanha(cc0);
        h1f = sigf(ov.y)*tanha(cc1);
        __half* hn = hb + ((t&1)^1)*8*HSTR;
        hn[r0a*HSTR + mycol]     = __float2half(h0f);
        hn[(r0a+1)*HSTR + mycol] = __float2half(h1f);

        STAGEX(t+2);
    }
    g_hlast[(bid*8 + r0a)*HID + mycol]   = h0f;
    g_hlast[(bid*8 + r0a+1)*HID + mycol] = h1f;
#undef STAGEX
}

// ---------------- dense + softmax (2 batch rows / block) ----------------
__global__ void __launch_bounds__(512) k_dense2(const float* __restrict__ wd,
                                                const float* __restrict__ bd,
                                                float* __restrict__ out){
    int b0=blockIdx.x*2, tid=threadIdx.x, lane=tid&31, warp=tid>>5;
    __shared__ float hs[2*HID];
    __shared__ float lg[2*OUTSZ];
    __shared__ float red[32];
    if (tid<2*HID) hs[tid]=g_hlast[b0*HID+tid];
    __syncthreads();
    const float4* h0=(const float4*)hs;
    const float4* h1=(const float4*)(hs+HID);
    for (int o=tid; o<OUTSZ; o+=512){
        const float4* wp=(const float4*)(wd+(size_t)o*HID);
        float s0=0.f, s1=0.f;
#pragma unroll 8
        for (int q=0;q<32;q++){
            float4 v=wp[q]; float4 a=h0[q]; float4 b=h1[q];
            s0 += v.x*a.x+v.y*a.y+v.z*a.z+v.w*a.w;
            s1 += v.x*b.x+v.y*b.y+v.z*b.z+v.w*b.w;
        }
        float bb=bd[o];
        lg[o]=s0+bb; lg[OUTSZ+o]=s1+bb;
    }
    __syncthreads();
    float m0=-1e30f, m1=-1e30f;
    for (int i=tid;i<OUTSZ;i+=512){ m0=fmaxf(m0,lg[i]); m1=fmaxf(m1,lg[OUTSZ+i]); }
#pragma unroll
    for (int s=16;s;s>>=1){ m0=fmaxf(m0,__shfl_xor_sync(0xffffffffu,m0,s));
                            m1=fmaxf(m1,__shfl_xor_sync(0xffffffffu,m1,s)); }
    if (lane==0){ red[warp]=m0; red[16+warp]=m1; }
    __syncthreads();
    m0=red[0]; m1=red[16];
#pragma unroll
    for (int ww=1;ww<16;ww++){ m0=fmaxf(m0,red[ww]); m1=fmaxf(m1,red[16+ww]); }
    float s0=0.f, s1=0.f;
    for (int i=tid;i<OUTSZ;i+=512){
        float e0=__expf(lg[i]-m0);       lg[i]=e0;       s0+=e0;
        float e1=__expf(lg[OUTSZ+i]-m1); lg[OUTSZ+i]=e1; s1+=e1;
    }
#pragma unroll
    for (int s=16;s;s>>=1){ s0+=__shfl_xor_sync(0xffffffffu,s0,s);
                            s1+=__shfl_xor_sync(0xffffffffu,s1,s); }
    __syncthreads();
    if (lane==0){ red[warp]=s0; red[16+warp]=s1; }
    __syncthreads();
    s0=red[0]; s1=red[16];
#pragma unroll
    for (int ww=1;ww<16;ww++){ s0+=red[ww]; s1+=red[16+ww]; }
    float inv0=1.0f/s0, inv1=1.0f/s1;
    for (int i=tid;i<OUTSZ;i+=512){
        out[(size_t)b0*OUTSZ+i]     = lg[i]*inv0;
        out[(size_t)(b0+1)*OUTSZ+i] = lg[OUTSZ+i]*inv1;
    }
}

// ---------------- launcher ----------------
extern "C" void kernel_launch(void* const* d_in, const int* in_sizes, int n_in,
                              void* d_out, int out_size){
    const float* x=(const float*)d_in[0];
    const float* wih=(const float*)d_in[1];
    const float* whh=(const float*)d_in[2];
    const float* bih=(const float*)d_in[3];
    const float* bhh=(const float*)d_in[4];
    const float* wd=(const float*)d_in[5];
    const float* bd=(const float*)d_in[6];
    float* out=(float*)d_out;

    int fsm = (128*LDA + 2*64*LDA)*2 + 128*LDC*4;      // 169984 B (gemm governs)
    cudaFuncSetAttribute(k_fused, cudaFuncAttributeMaxDynamicSharedMemorySize, fsm);

    k_prep<<<512,256>>>(wih,whh,bih,bhh);
    k_dummy<<<1,32>>>();                               // keep k_fused as ncu's 4th launch
    k_dummy<<<1,32>>>();
    k_fused<<<148,512,fsm>>>(x);
    k_dense2<<<BATCH/2,512>>>(wd,bd,out);
}